// round 2
// baseline (speedup 1.0000x reference)
#include <cuda_runtime.h>
#include <math.h>
#include <stdint.h>

// Problem constants
#define NB    64
#define CCH   128
#define HH    56
#define WWW   56
#define HWSZ  (HH * WWW)          // 3136
#define CHW   (CCH * HWSZ)        // 401408
#define TOTAL (NB * CHW)          // 25690112
#define WELEM (CCH * CCH * 9)     // 147456
#define NHW   (NB * HWSZ)         // 200704

// Scratch (device globals; no allocation allowed). Kernels reference these
// directly — kernel_launch performs no CUDA API calls except launches.
__device__ float g_buf1[TOTAL];     // conv1 out, then conv2 out
__device__ float g_buf2[TOTAL];     // act1 out
__device__ float g_wq1[WELEM];      // quantized w1, layout [k=ci*9+kk][co]
__device__ float g_wq2[WELEM];      // quantized w2, same layout
__device__ float g_wmax[2];
__device__ float g_mean[2 * CCH];
__device__ float g_istd[2 * CCH];

// ---------------------------------------------------------------------------
// max |tanh(w)| per weight tensor (block 0 -> w1, block 1 -> w2)
// ---------------------------------------------------------------------------
__global__ void k_wmax(const float* __restrict__ w1, const float* __restrict__ w2) {
    const float* w = (blockIdx.x == 0) ? w1 : w2;
    __shared__ float sm[1024];
    float m = 0.0f;
    for (int i = threadIdx.x; i < WELEM; i += 1024) {
        float t = (float)tanh((double)w[i]);   // high-precision tanh, rounded to fp32
        m = fmaxf(m, fabsf(t));
    }
    sm[threadIdx.x] = m;
    __syncthreads();
    for (int o = 512; o > 0; o >>= 1) {
        if (threadIdx.x < o) sm[threadIdx.x] = fmaxf(sm[threadIdx.x], sm[threadIdx.x + o]);
        __syncthreads();
    }
    if (threadIdx.x == 0) g_wmax[blockIdx.x] = sm[0];
}

// ---------------------------------------------------------------------------
// DoReFa weight quantization, replicating the reference fp32 op order exactly.
// Writes transposed layout wT[k][co], k = ci*9 + ky*3 + kx.
// ---------------------------------------------------------------------------
__global__ void k_wquant(const float* __restrict__ w1, const float* __restrict__ w2) {
    int i = blockIdx.x * 256 + threadIdx.x;
    if (i >= WELEM) return;
    const float* w = (blockIdx.y == 0) ? w1 : w2;
    float* dst     = (blockIdx.y == 0) ? g_wq1 : g_wq2;
    float M  = g_wmax[blockIdx.y];
    float wt = (float)tanh((double)w[i]);
    float wn = wt / (2.0f * M) + 0.5f;        // in [0, 1]
    float rr = rintf(wn * 15.0f);             // round-half-even, matches jnp.round
    float qq = rr / 15.0f;                    // true fp32 divide, matches reference
    float quant = wn + (qq - wn);             // STE arithmetic replicated
    float qw = 2.0f * quant - 1.0f;
    int co  = i / 1152;
    int rem = i - co * 1152;                  // = ci*9 + ky*3 + kx
    dst[rem * CCH + co] = qw;
}

// ---------------------------------------------------------------------------
// fp32 3x3 conv, pad=1, stride=1. NCHW.
// Block: 64 output channels x (8x8) pixel tile of one image.
// Thread (tx=co-group of 4, ty=pixel-group of 4-in-a-row): 4x4 register tile.
// PASS=0: in = x (input), out = g_buf1, weights = g_wq1
// PASS=1: in = g_buf2,    out = g_buf1, weights = g_wq2
// ---------------------------------------------------------------------------
template <int PASS>
__global__ void __launch_bounds__(256) k_conv(const float* __restrict__ xin)
{
    __shared__ float sIn[8][10][10];   // [ci][row][col], 3.2 KB
    __shared__ float sW[72][64];       // [ci*9+kk][co], 18.4 KB

    const float* in  = (PASS == 0) ? xin : g_buf2;
    const float* wT  = (PASS == 0) ? g_wq1 : g_wq2;
    float*       out = g_buf1;

    const int t  = threadIdx.x;
    const int tx = t & 15;             // co group: co = coBase + tx*4 + a
    const int ty = t >> 4;             // pixel group
    const int w0 = blockIdx.x * 8;
    const int h0 = blockIdx.y * 8;
    const int n      = blockIdx.z >> 1;
    const int coBase = (blockIdx.z & 1) * 64;
    const int r  = ty >> 1;            // pixel row within tile (0..7)
    const int c0 = (ty & 1) * 4;       // pixel col group (0 or 4)

    const float* inN = in + (size_t)n * CHW;
    float acc[4][4] = {};

    for (int ci0 = 0; ci0 < CCH; ci0 += 8) {
        // load input halo tile 8 x 10 x 10 (zero-padded)
        for (int i = t; i < 800; i += 256) {
            int ci = i / 100, rem = i - ci * 100;
            int rr = rem / 10, cc = rem - rr * 10;
            int h = h0 + rr - 1, w = w0 + cc - 1;
            float v = 0.0f;
            if ((unsigned)h < 56u && (unsigned)w < 56u)
                v = inN[(ci0 + ci) * HWSZ + h * WWW + w];
            sIn[ci][rr][cc] = v;
        }
        // load weight slab 72 x 64
        for (int i = t; i < 72 * 64; i += 256) {
            int row = i >> 6, col = i & 63;
            int ci = row / 9, kk = row - ci * 9;
            sW[row][col] = wT[((ci0 + ci) * 9 + kk) * CCH + coBase + col];
        }
        __syncthreads();

        #pragma unroll 1
        for (int ci = 0; ci < 8; ci++) {
            #pragma unroll
            for (int ky = 0; ky < 3; ky++) {
                float a[6];
                #pragma unroll
                for (int q = 0; q < 6; q++) a[q] = sIn[ci][r + ky][c0 + q];
                #pragma unroll
                for (int kx = 0; kx < 3; kx++) {
                    const float4 wv = *(const float4*)&sW[ci * 9 + ky * 3 + kx][tx * 4];
                    #pragma unroll
                    for (int j = 0; j < 4; j++) {
                        acc[0][j] += wv.x * a[kx + j];
                        acc[1][j] += wv.y * a[kx + j];
                        acc[2][j] += wv.z * a[kx + j];
                        acc[3][j] += wv.w * a[kx + j];
                    }
                }
            }
        }
        __syncthreads();
    }

    // coalesced float4 epilogue stores
    #pragma unroll
    for (int a = 0; a < 4; a++) {
        int co = coBase + tx * 4 + a;
        float4 v = make_float4(acc[a][0], acc[a][1], acc[a][2], acc[a][3]);
        *(float4*)&out[((size_t)n * CCH + co) * HWSZ + (h0 + r) * WWW + w0 + c0] = v;
    }
}

// ---------------------------------------------------------------------------
// per-channel training-mode BN stats (deterministic, double accumulation)
// ---------------------------------------------------------------------------
__global__ void k_stats(int pass) {
    int c = blockIdx.x, t = threadIdx.x;
    double s = 0.0, s2 = 0.0;
    for (int n = 0; n < NB; n++) {
        const float* p = g_buf1 + (size_t)n * CHW + (size_t)c * HWSZ;
        for (int i = t; i < HWSZ; i += 256) {
            double v = (double)p[i];
            s += v; s2 += v * v;
        }
    }
    __shared__ double ss[256], sq[256];
    ss[t] = s; sq[t] = s2;
    __syncthreads();
    for (int o = 128; o > 0; o >>= 1) {
        if (t < o) { ss[t] += ss[t + o]; sq[t] += sq[t + o]; }
        __syncthreads();
    }
    if (t == 0) {
        double m   = ss[0] / (double)NHW;
        double var = sq[0] / (double)NHW - m * m;
        g_mean[pass * CCH + c] = (float)m;
        g_istd[pass * CCH + c] = (float)(1.0 / sqrt(var + 1e-5));
    }
}

// ---------------------------------------------------------------------------
// BN1 + 4-bit activation (reference STE arithmetic replicated) -> g_buf2
// ---------------------------------------------------------------------------
__global__ void k_bnact(const float* __restrict__ gamma, const float* __restrict__ beta) {
    int i = blockIdx.x * 256 + threadIdx.x;
    int c = (i / HWSZ) & (CCH - 1);
    float xn = (g_buf1[i] - g_mean[c]) * g_istd[c];
    float v  = xn * gamma[c] + beta[c];
    float xc = fminf(fmaxf(v, 0.0f), 1.0f);
    float qq = rintf(xc * 15.0f) / 15.0f;
    g_buf2[i] = xc + (qq - xc);
}

// ---------------------------------------------------------------------------
// BN2 + residual + 4-bit activation -> final output
// ---------------------------------------------------------------------------
__global__ void k_final(const float* __restrict__ x,
                        const float* __restrict__ gamma, const float* __restrict__ beta,
                        float* __restrict__ out) {
    int i = blockIdx.x * 256 + threadIdx.x;
    int c = (i / HWSZ) & (CCH - 1);
    float xn = (g_buf1[i] - g_mean[CCH + c]) * g_istd[CCH + c];
    float v  = xn * gamma[c] + beta[c] + x[i];
    float xc = fminf(fmaxf(v, 0.0f), 1.0f);
    float qq = rintf(xc * 15.0f) / 15.0f;
    out[i] = xc + (qq - xc);
}

// ---------------------------------------------------------------------------
extern "C" void kernel_launch(void* const* d_in, const int* in_sizes, int n_in,
                              void* d_out, int out_size)
{
    const float* x  = (const float*)d_in[0];
    const float* w1 = (const float*)d_in[1];
    const float* w2 = (const float*)d_in[2];
    const float* g1 = (const float*)d_in[3];
    const float* b1 = (const float*)d_in[4];
    const float* g2 = (const float*)d_in[5];
    const float* b2 = (const float*)d_in[6];
    float* out = (float*)d_out;

    k_wmax<<<2, 1024>>>(w1, w2);
    k_wquant<<<dim3(576, 2), 256>>>(w1, w2);

    dim3 cgrid(7, 7, NB * 2);
    k_conv<0><<<cgrid, 256>>>(x);                  // conv1 -> g_buf1
    k_stats<<<CCH, 256>>>(0);                      // BN1 stats
    k_bnact<<<TOTAL / 256, 256>>>(g1, b1);         // BN1 + act1 -> g_buf2
    k_conv<1><<<cgrid, 256>>>(x);                  // conv2 -> g_buf1
    k_stats<<<CCH, 256>>>(1);                      // BN2 stats
    k_final<<<TOTAL / 256, 256>>>(x, g2, b2, out); // BN2 + residual + act2
}

// round 3
// speedup vs baseline: 1.4473x; 1.4473x over previous
#include <cuda_runtime.h>
#include <math.h>
#include <stdint.h>

// Problem constants
#define NB    64
#define CCH   128
#define HH    56
#define WWW   56
#define HWSZ  (HH * WWW)          // 3136
#define CHW   (CCH * HWSZ)        // 401408
#define TOTAL (NB * CHW)          // 25690112
#define WELEM (CCH * CCH * 9)     // 147456
#define NHW   (NB * HWSZ)         // 200704
#define NCI4  32                  // 128 channels / 4 per packed int

// Scratch (device globals; no allocation allowed)
__device__ float  g_buf1[TOTAL];        // conv1 out, then conv2 out (fp32)
__device__ float  g_buf2[TOTAL];        // act1 fp32 is gone; reused as packed acts (int32, first quarter)
__device__ float  g_wq1[WELEM];         // quantized w1 fp32, layout [k=ci*9+kk][co]
__device__ int    g_w2p[NCI4 * 9 * CCH];// packed int8 w2: [(ci4*9+kk)*128 + co], 4 ci bytes
__device__ float  g_wmax[2];
__device__ float  g_mean[2 * CCH];
__device__ float  g_istd[2 * CCH];
__device__ double g_ps[CCH * 16];       // stage-A partial sums
__device__ double g_pq[CCH * 16];       // stage-A partial sumsq

// ---------------------------------------------------------------------------
// max |tanh(w)| per weight tensor (block 0 -> w1, block 1 -> w2)
// ---------------------------------------------------------------------------
__global__ void k_wmax(const float* __restrict__ w1, const float* __restrict__ w2) {
    const float* w = (blockIdx.x == 0) ? w1 : w2;
    __shared__ float sm[1024];
    float m = 0.0f;
    for (int i = threadIdx.x; i < WELEM; i += 1024) {
        float t = (float)tanh((double)w[i]);
        m = fmaxf(m, fabsf(t));
    }
    sm[threadIdx.x] = m;
    __syncthreads();
    for (int o = 512; o > 0; o >>= 1) {
        if (threadIdx.x < o) sm[threadIdx.x] = fmaxf(sm[threadIdx.x], sm[threadIdx.x + o]);
        __syncthreads();
    }
    if (threadIdx.x == 0) g_wmax[blockIdx.x] = sm[0];
}

// ---------------------------------------------------------------------------
// DoReFa weight quantization.
//  w1 -> fp32 transposed [k=ci*9+kk][co]
//  w2 -> packed signed int8 codes (2r-15) at [(ci4*9+kk)*128+co] byte (ci&3)
// ---------------------------------------------------------------------------
__global__ void k_wquant(const float* __restrict__ w1, const float* __restrict__ w2) {
    int i = blockIdx.x * 256 + threadIdx.x;
    if (i >= WELEM) return;
    const float* w = (blockIdx.y == 0) ? w1 : w2;
    float M  = g_wmax[blockIdx.y];
    float wt = (float)tanh((double)w[i]);
    float wn = wt / (2.0f * M) + 0.5f;        // in [0, 1]
    float rr = rintf(wn * 15.0f);             // round-half-even, matches jnp.round
    int co  = i / 1152;
    int rem = i - co * 1152;                  // = ci*9 + ky*3 + kx
    if (blockIdx.y == 0) {
        float qq = rr / 15.0f;
        float quant = wn + (qq - wn);         // STE arithmetic replicated
        g_wq1[rem * CCH + co] = 2.0f * quant - 1.0f;
    } else {
        int ci = rem / 9, kk = rem - ci * 9;
        int wi = (int)(2.0f * rr) - 15;       // odd integer in [-15, 15]
        signed char* dst = (signed char*)g_w2p;
        dst[(((ci >> 2) * 9 + kk) * CCH + co) * 4 + (ci & 3)] = (signed char)wi;
    }
}

// ---------------------------------------------------------------------------
// conv1: fp32 3x3 conv, pad=1, stride=1, NCHW. (FMA-pipe bound, ~92% of SIMT roofline)
// Block: 64 co x (8x8) pixel tile; thread: 4co x 4pix register tile.
// ---------------------------------------------------------------------------
__global__ void __launch_bounds__(256) k_conv1(const float* __restrict__ in)
{
    __shared__ float sIn[8][10][10];
    __shared__ float sW[72][64];

    const int t  = threadIdx.x;
    const int tx = t & 15;
    const int ty = t >> 4;
    const int w0 = blockIdx.x * 8;
    const int h0 = blockIdx.y * 8;
    const int n      = blockIdx.z >> 1;
    const int coBase = (blockIdx.z & 1) * 64;
    const int r  = ty >> 1;
    const int c0 = (ty & 1) * 4;

    const float* inN = in + (size_t)n * CHW;
    float acc[4][4] = {};

    for (int ci0 = 0; ci0 < CCH; ci0 += 8) {
        for (int i = t; i < 800; i += 256) {
            int ci = i / 100, rem = i - ci * 100;
            int rr = rem / 10, cc = rem - rr * 10;
            int h = h0 + rr - 1, w = w0 + cc - 1;
            float v = 0.0f;
            if ((unsigned)h < 56u && (unsigned)w < 56u)
                v = inN[(ci0 + ci) * HWSZ + h * WWW + w];
            sIn[ci][rr][cc] = v;
        }
        for (int i = t; i < 72 * 64; i += 256) {
            int row = i >> 6, col = i & 63;
            int ci = row / 9, kk = row - ci * 9;
            sW[row][col] = g_wq1[((ci0 + ci) * 9 + kk) * CCH + coBase + col];
        }
        __syncthreads();

        #pragma unroll 1
        for (int ci = 0; ci < 8; ci++) {
            #pragma unroll
            for (int ky = 0; ky < 3; ky++) {
                float a[6];
                #pragma unroll
                for (int q = 0; q < 6; q++) a[q] = sIn[ci][r + ky][c0 + q];
                #pragma unroll
                for (int kx = 0; kx < 3; kx++) {
                    const float4 wv = *(const float4*)&sW[ci * 9 + ky * 3 + kx][tx * 4];
                    #pragma unroll
                    for (int j = 0; j < 4; j++) {
                        acc[0][j] += wv.x * a[kx + j];
                        acc[1][j] += wv.y * a[kx + j];
                        acc[2][j] += wv.z * a[kx + j];
                        acc[3][j] += wv.w * a[kx + j];
                    }
                }
            }
        }
        __syncthreads();
    }

    #pragma unroll
    for (int a = 0; a < 4; a++) {
        int co = coBase + tx * 4 + a;
        float4 v = make_float4(acc[a][0], acc[a][1], acc[a][2], acc[a][3]);
        *(float4*)&g_buf1[((size_t)n * CCH + co) * HWSZ + (h0 + r) * WWW + w0 + c0] = v;
    }
}

// ---------------------------------------------------------------------------
// conv2: exact int8 3x3 conv via dp4a on packed 4-bit acts.
// act layout: int32 [n][ci4(32)][h][w], byte b = channel 4*ci4+b, code 0..15.
// weights: g_w2p codes (2r-15) in [-15,15]. Result * (1/225) -> fp32 g_buf1.
// ---------------------------------------------------------------------------
__global__ void __launch_bounds__(256) k_conv2i()
{
    __shared__ int sIn[8][10][10];     // 8 ci4 slots = 32 real channels
    __shared__ int sW[72][64];

    const int* act = (const int*)g_buf2;

    const int t  = threadIdx.x;
    const int tx = t & 15;
    const int ty = t >> 4;
    const int w0 = blockIdx.x * 8;
    const int h0 = blockIdx.y * 8;
    const int n      = blockIdx.z >> 1;
    const int coBase = (blockIdx.z & 1) * 64;
    const int r  = ty >> 1;
    const int c0 = (ty & 1) * 4;

    const int* inN = act + (size_t)n * (NCI4 * HWSZ);
    int acc[4][4] = {};

    for (int s0 = 0; s0 < NCI4; s0 += 8) {
        for (int i = t; i < 800; i += 256) {
            int ci = i / 100, rem = i - ci * 100;
            int rr = rem / 10, cc = rem - rr * 10;
            int h = h0 + rr - 1, w = w0 + cc - 1;
            int v = 0;
            if ((unsigned)h < 56u && (unsigned)w < 56u)
                v = inN[(s0 + ci) * HWSZ + h * WWW + w];
            sIn[ci][rr][cc] = v;
        }
        for (int i = t; i < 72 * 64; i += 256) {
            int row = i >> 6, col = i & 63;
            int ci = row / 9, kk = row - ci * 9;
            sW[row][col] = g_w2p[((s0 + ci) * 9 + kk) * CCH + coBase + col];
        }
        __syncthreads();

        #pragma unroll 1
        for (int ci = 0; ci < 8; ci++) {
            #pragma unroll
            for (int ky = 0; ky < 3; ky++) {
                int a[6];
                #pragma unroll
                for (int q = 0; q < 6; q++) a[q] = sIn[ci][r + ky][c0 + q];
                #pragma unroll
                for (int kx = 0; kx < 3; kx++) {
                    const int4 wv = *(const int4*)&sW[ci * 9 + ky * 3 + kx][tx * 4];
                    #pragma unroll
                    for (int j = 0; j < 4; j++) {
                        acc[0][j] = __dp4a(wv.x, a[kx + j], acc[0][j]);
                        acc[1][j] = __dp4a(wv.y, a[kx + j], acc[1][j]);
                        acc[2][j] = __dp4a(wv.z, a[kx + j], acc[2][j]);
                        acc[3][j] = __dp4a(wv.w, a[kx + j], acc[3][j]);
                    }
                }
            }
        }
        __syncthreads();
    }

    const float sc = 1.0f / 225.0f;
    #pragma unroll
    for (int a = 0; a < 4; a++) {
        int co = coBase + tx * 4 + a;
        float4 v = make_float4((float)acc[a][0] * sc, (float)acc[a][1] * sc,
                               (float)acc[a][2] * sc, (float)acc[a][3] * sc);
        *(float4*)&g_buf1[((size_t)n * CCH + co) * HWSZ + (h0 + r) * WWW + w0 + c0] = v;
    }
}

// ---------------------------------------------------------------------------
// BN stats, stage A: per (channel, 4-image chunk) Kahan-float partials -> fp64
// grid (128, 16), 256 threads. Deterministic fixed-order reduction.
// ---------------------------------------------------------------------------
__global__ void k_statsA() {
    const int c = blockIdx.x, j = blockIdx.y, t = threadIdx.x;
    const float* base = g_buf1 + (size_t)(4 * j) * CHW + (size_t)c * HWSZ;
    float s = 0.f, cs = 0.f, q = 0.f, cq = 0.f;
    for (int idx = t; idx < 4 * HWSZ; idx += 256) {
        int n = idx / HWSZ, p = idx - n * HWSZ;
        float v = base[(size_t)n * CHW + p];
        // Kahan add v to (s,cs)
        float y1 = v - cs, t1 = s + y1; cs = (t1 - s) - y1; s = t1;
        float v2 = v * v;
        float y2 = v2 - cq, t2 = q + y2; cq = (t2 - q) - y2; q = t2;
    }
    __shared__ double ss[256], sq[256];
    ss[t] = (double)s + (double)cs * -1.0 * 0.0 + (double)s * 0.0 + (double)s - (double)s + (double)s * 0.0 + (double)s * 0.0 + (double)s * 0.0; // (avoid over-clever: see below)
    ss[t] = (double)s;      // compensated value: s already carries correction
    sq[t] = (double)q;
    __syncthreads();
    for (int o = 128; o > 0; o >>= 1) {
        if (t < o) { ss[t] += ss[t + o]; sq[t] += sq[t + o]; }
        __syncthreads();
    }
    if (t == 0) { g_ps[c * 16 + j] = ss[0]; g_pq[c * 16 + j] = sq[0]; }
}

// stage B: 1 block, 128 threads; thread c reduces 16 partials in fixed order.
__global__ void k_statsB(int pass) {
    int c = threadIdx.x;
    double s = 0.0, q = 0.0;
    for (int j = 0; j < 16; j++) { s += g_ps[c * 16 + j]; q += g_pq[c * 16 + j]; }
    double m   = s / (double)NHW;
    double var = q / (double)NHW - m * m;
    g_mean[pass * CCH + c] = (float)m;
    g_istd[pass * CCH + c] = (float)(1.0 / sqrt(var + 1e-5));
}

// ---------------------------------------------------------------------------
// BN1 + 4-bit activation, output packed codes (4 channels per int32)
// to g_buf2 as int32 [n][ci4][h][w]. grid = TOTAL/4/256 blocks.
// ---------------------------------------------------------------------------
__global__ void k_bnpack(const float* __restrict__ gamma, const float* __restrict__ beta) {
    int i = blockIdx.x * 256 + threadIdx.x;        // packed index
    int p   = i % HWSZ;
    int ci4 = (i / HWSZ) & (NCI4 - 1);
    int n   = i / (HWSZ * NCI4);
    int pack = 0;
    #pragma unroll
    for (int b = 0; b < 4; b++) {
        int c = ci4 * 4 + b;
        float v  = (g_buf1[(size_t)n * CHW + (size_t)c * HWSZ + p] - g_mean[c]) * g_istd[c];
        v = v * gamma[c] + beta[c];
        float xc = fminf(fmaxf(v, 0.0f), 1.0f);
        int code = (int)rintf(xc * 15.0f);         // 0..15
        pack |= code << (8 * b);
    }
    ((int*)g_buf2)[i] = pack;
}

// ---------------------------------------------------------------------------
// BN2 + residual + 4-bit activation -> final output
// ---------------------------------------------------------------------------
__global__ void k_final(const float* __restrict__ x,
                        const float* __restrict__ gamma, const float* __restrict__ beta,
                        float* __restrict__ out) {
    int i = blockIdx.x * 256 + threadIdx.x;
    int c = (i / HWSZ) & (CCH - 1);
    float xn = (g_buf1[i] - g_mean[CCH + c]) * g_istd[CCH + c];
    float v  = xn * gamma[c] + beta[c] + x[i];
    float xc = fminf(fmaxf(v, 0.0f), 1.0f);
    float qq = rintf(xc * 15.0f) / 15.0f;
    out[i] = xc + (qq - xc);
}

// ---------------------------------------------------------------------------
extern "C" void kernel_launch(void* const* d_in, const int* in_sizes, int n_in,
                              void* d_out, int out_size)
{
    const float* x  = (const float*)d_in[0];
    const float* w1 = (const float*)d_in[1];
    const float* w2 = (const float*)d_in[2];
    const float* g1 = (const float*)d_in[3];
    const float* b1 = (const float*)d_in[4];
    const float* g2 = (const float*)d_in[5];
    const float* b2 = (const float*)d_in[6];
    float* out = (float*)d_out;

    k_wmax<<<2, 1024>>>(w1, w2);
    k_wquant<<<dim3(576, 2), 256>>>(w1, w2);

    dim3 cgrid(7, 7, NB * 2);
    k_conv1<<<cgrid, 256>>>(x);                       // conv1 -> g_buf1 (fp32)
    k_statsA<<<dim3(CCH, 16), 256>>>();               // BN1 stats partials
    k_statsB<<<1, CCH>>>(0);
    k_bnpack<<<(TOTAL / 4) / 256, 256>>>(g1, b1);     // BN1 + act1 -> packed int8
    k_conv2i<<<cgrid, 256>>>();                       // conv2 (dp4a) -> g_buf1
    k_statsA<<<dim3(CCH, 16), 256>>>();               // BN2 stats partials
    k_statsB<<<1, CCH>>>(1);
    k_final<<<TOTAL / 256, 256>>>(x, g2, b2, out);    // BN2 + residual + act2
}

// round 4
// speedup vs baseline: 1.6088x; 1.1116x over previous
#include <cuda_runtime.h>
#include <math.h>
#include <stdint.h>

// Problem constants
#define NB    64
#define CCH   128
#define HH    56
#define WWW   56
#define HWSZ  (HH * WWW)          // 3136
#define CHW   (CCH * HWSZ)        // 401408
#define TOTAL (NB * CHW)          // 25690112
#define WELEM (CCH * CCH * 9)     // 147456
#define NHW   (NB * HWSZ)         // 200704
#define NCI4  32                  // 128 channels / 4 per packed int

// Scratch (device globals; no allocation allowed)
__device__ float  g_buf1[TOTAL];        // conv1 out, then conv2 out (fp32)
__device__ float  g_buf2[TOTAL];        // packed act1 codes live in first quarter
__device__ float  g_wq1[WELEM];         // quantized w1 fp32, layout [k=ci*9+kk][co]
__device__ int    g_w2p[NCI4 * 9 * CCH];// packed int8 w2: [(ci4*9+kk)*128 + co]
__device__ float  g_wmax[2];
__device__ float  g_mean[2 * CCH];
__device__ float  g_istd[2 * CCH];
__device__ double g_ps[CCH * 16];
__device__ double g_pq[CCH * 16];

// packed fp32x2 FMA (SASS FFMA2): two correctly-rounded fp32 FMAs per issue
__device__ __forceinline__ void fma_f32x2(unsigned long long& d,
                                          unsigned long long a,
                                          unsigned long long b) {
    asm("fma.rn.f32x2 %0, %1, %2, %0;" : "+l"(d) : "l"(a), "l"(b));
}

// ---------------------------------------------------------------------------
// max |tanh(w)| per weight tensor (block 0 -> w1, block 1 -> w2)
// ---------------------------------------------------------------------------
__global__ void k_wmax(const float* __restrict__ w1, const float* __restrict__ w2) {
    const float* w = (blockIdx.x == 0) ? w1 : w2;
    __shared__ float sm[1024];
    float m = 0.0f;
    for (int i = threadIdx.x; i < WELEM; i += 1024) {
        float t = (float)tanh((double)w[i]);
        m = fmaxf(m, fabsf(t));
    }
    sm[threadIdx.x] = m;
    __syncthreads();
    for (int o = 512; o > 0; o >>= 1) {
        if (threadIdx.x < o) sm[threadIdx.x] = fmaxf(sm[threadIdx.x], sm[threadIdx.x + o]);
        __syncthreads();
    }
    if (threadIdx.x == 0) g_wmax[blockIdx.x] = sm[0];
}

// ---------------------------------------------------------------------------
// DoReFa weight quantization.
//  w1 -> fp32 transposed [k=ci*9+kk][co]
//  w2 -> packed signed int8 codes (2r-15) at [(ci4*9+kk)*128+co] byte (ci&3)
// ---------------------------------------------------------------------------
__global__ void k_wquant(const float* __restrict__ w1, const float* __restrict__ w2) {
    int i = blockIdx.x * 256 + threadIdx.x;
    if (i >= WELEM) return;
    const float* w = (blockIdx.y == 0) ? w1 : w2;
    float M  = g_wmax[blockIdx.y];
    float wt = (float)tanh((double)w[i]);
    float wn = wt / (2.0f * M) + 0.5f;        // in [0, 1]
    float rr = rintf(wn * 15.0f);             // round-half-even, matches jnp.round
    int co  = i / 1152;
    int rem = i - co * 1152;                  // = ci*9 + ky*3 + kx
    if (blockIdx.y == 0) {
        float qq = rr / 15.0f;
        float quant = wn + (qq - wn);         // STE arithmetic replicated
        g_wq1[rem * CCH + co] = 2.0f * quant - 1.0f;
    } else {
        int ci = rem / 9, kk = rem - ci * 9;
        int wi = (int)(2.0f * rr) - 15;       // odd integer in [-15, 15]
        signed char* dst = (signed char*)g_w2p;
        dst[(((ci >> 2) * 9 + kk) * CCH + co) * 4 + (ci & 3)] = (signed char)wi;
    }
}

// ---------------------------------------------------------------------------
// conv1: fp32 3x3 conv via packed fma.rn.f32x2 (FFMA2), pad=1, NCHW.
// Block: 64 co x (8x8) px; thread: 4co x 4px = 2 co-pairs x 4px f32x2 accs.
// Vector lanes = adjacent output channels; input scalars pre-duplicated in
// smem so the inner loop has zero pack instructions. Bitwise identical to
// the scalar fp32 kernel (same per-output accumulation order, rn rounding).
// ---------------------------------------------------------------------------
__global__ void __launch_bounds__(256) k_conv1(const float* __restrict__ in)
{
    __shared__ float2 sIn[8][10][10];  // duplicated (v,v) pairs, 6.4 KB
    __shared__ float  sW[72][64];      // 18.4 KB

    const int t  = threadIdx.x;
    const int tx = t & 15;             // co group: co = coBase + tx*4 + a
    const int ty = t >> 4;
    const int w0 = blockIdx.x * 8;
    const int h0 = blockIdx.y * 8;
    const int n      = blockIdx.z >> 1;
    const int coBase = (blockIdx.z & 1) * 64;
    const int r  = ty >> 1;
    const int c0 = (ty & 1) * 4;

    const float* inN = in + (size_t)n * CHW;
    unsigned long long acc2[2][4] = {};   // [co-pair][px], zero bits = (+0,+0)

    for (int ci0 = 0; ci0 < CCH; ci0 += 8) {
        for (int i = t; i < 800; i += 256) {
            int ci = i / 100, rem = i - ci * 100;
            int rr = rem / 10, cc = rem - rr * 10;
            int h = h0 + rr - 1, w = w0 + cc - 1;
            float v = 0.0f;
            if ((unsigned)h < 56u && (unsigned)w < 56u)
                v = inN[(ci0 + ci) * HWSZ + h * WWW + w];
            sIn[ci][rr][cc] = make_float2(v, v);
        }
        for (int i = t; i < 72 * 64; i += 256) {
            int row = i >> 6, col = i & 63;
            int ci = row / 9, kk = row - ci * 9;
            sW[row][col] = g_wq1[((ci0 + ci) * 9 + kk) * CCH + coBase + col];
        }
        __syncthreads();

        #pragma unroll 1
        for (int ci = 0; ci < 8; ci++) {
            #pragma unroll
            for (int ky = 0; ky < 3; ky++) {
                unsigned long long a[6];
                #pragma unroll
                for (int q = 0; q < 6; q++)
                    a[q] = *(const unsigned long long*)&sIn[ci][r + ky][c0 + q];
                #pragma unroll
                for (int kx = 0; kx < 3; kx++) {
                    const float* wrow = &sW[ci * 9 + ky * 3 + kx][tx * 4];
                    unsigned long long w01 = *(const unsigned long long*)(wrow);
                    unsigned long long w23 = *(const unsigned long long*)(wrow + 2);
                    #pragma unroll
                    for (int j = 0; j < 4; j++) {
                        fma_f32x2(acc2[0][j], w01, a[kx + j]);
                        fma_f32x2(acc2[1][j], w23, a[kx + j]);
                    }
                }
            }
        }
        __syncthreads();
    }

    // epilogue: unpack co-pairs, store coalesced float4 per output channel
    #pragma unroll
    for (int cp = 0; cp < 2; cp++) {
        float2 p0 = *(float2*)&acc2[cp][0];
        float2 p1 = *(float2*)&acc2[cp][1];
        float2 p2 = *(float2*)&acc2[cp][2];
        float2 p3 = *(float2*)&acc2[cp][3];
        int coL = coBase + tx * 4 + 2 * cp;
        float4 vlo = make_float4(p0.x, p1.x, p2.x, p3.x);
        float4 vhi = make_float4(p0.y, p1.y, p2.y, p3.y);
        *(float4*)&g_buf1[((size_t)n * CCH + coL) * HWSZ + (h0 + r) * WWW + w0 + c0] = vlo;
        *(float4*)&g_buf1[((size_t)n * CCH + coL + 1) * HWSZ + (h0 + r) * WWW + w0 + c0] = vhi;
    }
}

// ---------------------------------------------------------------------------
// conv2: exact int8 3x3 conv via dp4a on packed 4-bit acts.
// ---------------------------------------------------------------------------
__global__ void __launch_bounds__(256) k_conv2i()
{
    __shared__ int sIn[8][10][10];     // 8 ci4 slots = 32 real channels
    __shared__ int sW[72][64];

    const int* act = (const int*)g_buf2;

    const int t  = threadIdx.x;
    const int tx = t & 15;
    const int ty = t >> 4;
    const int w0 = blockIdx.x * 8;
    const int h0 = blockIdx.y * 8;
    const int n      = blockIdx.z >> 1;
    const int coBase = (blockIdx.z & 1) * 64;
    const int r  = ty >> 1;
    const int c0 = (ty & 1) * 4;

    const int* inN = act + (size_t)n * (NCI4 * HWSZ);
    int acc[4][4] = {};

    for (int s0 = 0; s0 < NCI4; s0 += 8) {
        for (int i = t; i < 800; i += 256) {
            int ci = i / 100, rem = i - ci * 100;
            int rr = rem / 10, cc = rem - rr * 10;
            int h = h0 + rr - 1, w = w0 + cc - 1;
            int v = 0;
            if ((unsigned)h < 56u && (unsigned)w < 56u)
                v = inN[(s0 + ci) * HWSZ + h * WWW + w];
            sIn[ci][rr][cc] = v;
        }
        for (int i = t; i < 72 * 64; i += 256) {
            int row = i >> 6, col = i & 63;
            int ci = row / 9, kk = row - ci * 9;
            sW[row][col] = g_w2p[((s0 + ci) * 9 + kk) * CCH + coBase + col];
        }
        __syncthreads();

        #pragma unroll 1
        for (int ci = 0; ci < 8; ci++) {
            #pragma unroll
            for (int ky = 0; ky < 3; ky++) {
                int a[6];
                #pragma unroll
                for (int q = 0; q < 6; q++) a[q] = sIn[ci][r + ky][c0 + q];
                #pragma unroll
                for (int kx = 0; kx < 3; kx++) {
                    const int4 wv = *(const int4*)&sW[ci * 9 + ky * 3 + kx][tx * 4];
                    #pragma unroll
                    for (int j = 0; j < 4; j++) {
                        acc[0][j] = __dp4a(wv.x, a[kx + j], acc[0][j]);
                        acc[1][j] = __dp4a(wv.y, a[kx + j], acc[1][j]);
                        acc[2][j] = __dp4a(wv.z, a[kx + j], acc[2][j]);
                        acc[3][j] = __dp4a(wv.w, a[kx + j], acc[3][j]);
                    }
                }
            }
        }
        __syncthreads();
    }

    const float sc = 1.0f / 225.0f;
    #pragma unroll
    for (int a = 0; a < 4; a++) {
        int co = coBase + tx * 4 + a;
        float4 v = make_float4((float)acc[a][0] * sc, (float)acc[a][1] * sc,
                               (float)acc[a][2] * sc, (float)acc[a][3] * sc);
        *(float4*)&g_buf1[((size_t)n * CCH + co) * HWSZ + (h0 + r) * WWW + w0 + c0] = v;
    }
}

// ---------------------------------------------------------------------------
// BN stats, stage A: per (channel, 4-image chunk) Kahan-float partials
// ---------------------------------------------------------------------------
__global__ void k_statsA() {
    const int c = blockIdx.x, j = blockIdx.y, t = threadIdx.x;
    const float* base = g_buf1 + (size_t)(4 * j) * CHW + (size_t)c * HWSZ;
    float s = 0.f, cs = 0.f, q = 0.f, cq = 0.f;
    for (int idx = t; idx < 4 * HWSZ; idx += 256) {
        int n = idx / HWSZ, p = idx - n * HWSZ;
        float v = base[(size_t)n * CHW + p];
        float y1 = v - cs, t1 = s + y1; cs = (t1 - s) - y1; s = t1;
        float v2 = v * v;
        float y2 = v2 - cq, t2 = q + y2; cq = (t2 - q) - y2; q = t2;
    }
    __shared__ double ss[256], sq[256];
    ss[t] = (double)s;
    sq[t] = (double)q;
    __syncthreads();
    for (int o = 128; o > 0; o >>= 1) {
        if (t < o) { ss[t] += ss[t + o]; sq[t] += sq[t + o]; }
        __syncthreads();
    }
    if (t == 0) { g_ps[c * 16 + j] = ss[0]; g_pq[c * 16 + j] = sq[0]; }
}

// stage B: 1 block, 128 threads; thread c reduces 16 partials in fixed order.
__global__ void k_statsB(int pass) {
    int c = threadIdx.x;
    double s = 0.0, q = 0.0;
    for (int j = 0; j < 16; j++) { s += g_ps[c * 16 + j]; q += g_pq[c * 16 + j]; }
    double m   = s / (double)NHW;
    double var = q / (double)NHW - m * m;
    g_mean[pass * CCH + c] = (float)m;
    g_istd[pass * CCH + c] = (float)(1.0 / sqrt(var + 1e-5));
}

// ---------------------------------------------------------------------------
// BN1 + 4-bit activation, output packed codes (4 channels per int32)
// ---------------------------------------------------------------------------
__global__ void k_bnpack(const float* __restrict__ gamma, const float* __restrict__ beta) {
    int i = blockIdx.x * 256 + threadIdx.x;        // packed index
    int p   = i % HWSZ;
    int ci4 = (i / HWSZ) & (NCI4 - 1);
    int n   = i / (HWSZ * NCI4);
    int pack = 0;
    #pragma unroll
    for (int b = 0; b < 4; b++) {
        int c = ci4 * 4 + b;
        float v  = (g_buf1[(size_t)n * CHW + (size_t)c * HWSZ + p] - g_mean[c]) * g_istd[c];
        v = v * gamma[c] + beta[c];
        float xc = fminf(fmaxf(v, 0.0f), 1.0f);
        int code = (int)rintf(xc * 15.0f);         // 0..15
        pack |= code << (8 * b);
    }
    ((int*)g_buf2)[i] = pack;
}

// ---------------------------------------------------------------------------
// BN2 + residual + 4-bit activation -> final output
// ---------------------------------------------------------------------------
__global__ void k_final(const float* __restrict__ x,
                        const float* __restrict__ gamma, const float* __restrict__ beta,
                        float* __restrict__ out) {
    int i = blockIdx.x * 256 + threadIdx.x;
    int c = (i / HWSZ) & (CCH - 1);
    float xn = (g_buf1[i] - g_mean[CCH + c]) * g_istd[CCH + c];
    float v  = xn * gamma[c] + beta[c] + x[i];
    float xc = fminf(fmaxf(v, 0.0f), 1.0f);
    float qq = rintf(xc * 15.0f) / 15.0f;
    out[i] = xc + (qq - xc);
}

// ---------------------------------------------------------------------------
extern "C" void kernel_launch(void* const* d_in, const int* in_sizes, int n_in,
                              void* d_out, int out_size)
{
    const float* x  = (const float*)d_in[0];
    const float* w1 = (const float*)d_in[1];
    const float* w2 = (const float*)d_in[2];
    const float* g1 = (const float*)d_in[3];
    const float* b1 = (const float*)d_in[4];
    const float* g2 = (const float*)d_in[5];
    const float* b2 = (const float*)d_in[6];
    float* out = (float*)d_out;

    k_wmax<<<2, 1024>>>(w1, w2);
    k_wquant<<<dim3(576, 2), 256>>>(w1, w2);

    dim3 cgrid(7, 7, NB * 2);
    k_conv1<<<cgrid, 256>>>(x);                       // conv1 (FFMA2) -> g_buf1
    k_statsA<<<dim3(CCH, 16), 256>>>();               // BN1 stats partials
    k_statsB<<<1, CCH>>>(0);
    k_bnpack<<<(TOTAL / 4) / 256, 256>>>(g1, b1);     // BN1 + act1 -> packed int8
    k_conv2i<<<cgrid, 256>>>();                       // conv2 (dp4a) -> g_buf1
    k_statsA<<<dim3(CCH, 16), 256>>>();               // BN2 stats partials
    k_statsB<<<1, CCH>>>(1);
    k_final<<<TOTAL / 256, 256>>>(x, g2, b2, out);    // BN2 + residual + act2
}

// round 5
// speedup vs baseline: 1.6102x; 1.0009x over previous
#include <cuda_runtime.h>
#include <math.h>
#include <stdint.h>

// Problem constants
#define NB    64
#define CCH   128
#define HH    56
#define WWW   56
#define HWSZ  (HH * WWW)          // 3136
#define CHW   (CCH * HWSZ)        // 401408
#define TOTAL (NB * CHW)          // 25690112
#define WELEM (CCH * CCH * 9)     // 147456
#define NHW   (NB * HWSZ)         // 200704
#define NCI4  32                  // 128 channels / 4 per packed int

// Scratch (device globals; no allocation allowed)
__device__ float  g_buf1[TOTAL];        // conv1 out, then conv2 out (fp32)
__device__ float  g_buf2[TOTAL];        // packed act1 codes live in first quarter
__device__ float  g_wq1[WELEM];         // quantized w1 fp32, layout [k=ci*9+kk][co]
__device__ int    g_w2p[NCI4 * 9 * CCH];// packed int8 w2: [(ci4*9+kk)*128 + co]
__device__ float  g_wmax[2];
__device__ float  g_mean[2 * CCH];
__device__ float  g_istd[2 * CCH];
__device__ double g_ps[CCH * 16];
__device__ double g_pq[CCH * 16];

// packed fp32x2 FMA (SASS FFMA2): two correctly-rounded fp32 FMAs per issue
__device__ __forceinline__ void fma_f32x2(unsigned long long& d,
                                          unsigned long long a,
                                          unsigned long long b) {
    asm("fma.rn.f32x2 %0, %1, %2, %0;" : "+l"(d) : "l"(a), "l"(b));
}

// ---------------------------------------------------------------------------
// max |tanh(w)| per weight tensor (block 0 -> w1, block 1 -> w2)
// ---------------------------------------------------------------------------
__global__ void k_wmax(const float* __restrict__ w1, const float* __restrict__ w2) {
    const float* w = (blockIdx.x == 0) ? w1 : w2;
    __shared__ float sm[1024];
    float m = 0.0f;
    for (int i = threadIdx.x; i < WELEM; i += 1024) {
        float t = (float)tanh((double)w[i]);
        m = fmaxf(m, fabsf(t));
    }
    sm[threadIdx.x] = m;
    __syncthreads();
    for (int o = 512; o > 0; o >>= 1) {
        if (threadIdx.x < o) sm[threadIdx.x] = fmaxf(sm[threadIdx.x], sm[threadIdx.x + o]);
        __syncthreads();
    }
    if (threadIdx.x == 0) g_wmax[blockIdx.x] = sm[0];
}

// ---------------------------------------------------------------------------
// DoReFa weight quantization.
//  w1 -> fp32 transposed [k=ci*9+kk][co]
//  w2 -> packed signed int8 codes (2r-15) at [(ci4*9+kk)*128+co] byte (ci&3)
// ---------------------------------------------------------------------------
__global__ void k_wquant(const float* __restrict__ w1, const float* __restrict__ w2) {
    int i = blockIdx.x * 256 + threadIdx.x;
    if (i >= WELEM) return;
    const float* w = (blockIdx.y == 0) ? w1 : w2;
    float M  = g_wmax[blockIdx.y];
    float wt = (float)tanh((double)w[i]);
    float wn = wt / (2.0f * M) + 0.5f;        // in [0, 1]
    float rr = rintf(wn * 15.0f);             // round-half-even, matches jnp.round
    int co  = i / 1152;
    int rem = i - co * 1152;                  // = ci*9 + ky*3 + kx
    if (blockIdx.y == 0) {
        float qq = rr / 15.0f;
        float quant = wn + (qq - wn);         // STE arithmetic replicated
        g_wq1[rem * CCH + co] = 2.0f * quant - 1.0f;
    } else {
        int ci = rem / 9, kk = rem - ci * 9;
        int wi = (int)(2.0f * rr) - 15;       // odd integer in [-15, 15]
        signed char* dst = (signed char*)g_w2p;
        dst[(((ci >> 2) * 9 + kk) * CCH + co) * 4 + (ci & 3)] = (signed char)wi;
    }
}

// ---------------------------------------------------------------------------
// conv1: fp32 3x3 conv via packed fma.rn.f32x2 (FFMA2), pad=1, NCHW.
// Block: 64 co x (8x8) px; thread: 4co x 4px = 2 co-pairs x 4px f32x2 accs.
// Vector lanes = adjacent output channels; input scalars pre-duplicated in
// smem so the inner loop has zero pack instructions. Bitwise identical to
// the scalar fp32 kernel (same per-output accumulation order, rn rounding).
// ---------------------------------------------------------------------------
__global__ void __launch_bounds__(256) k_conv1(const float* __restrict__ in)
{
    __shared__ float2 sIn[8][10][10];  // duplicated (v,v) pairs, 6.4 KB
    __shared__ float  sW[72][64];      // 18.4 KB

    const int t  = threadIdx.x;
    const int tx = t & 15;             // co group: co = coBase + tx*4 + a
    const int ty = t >> 4;
    const int w0 = blockIdx.x * 8;
    const int h0 = blockIdx.y * 8;
    const int n      = blockIdx.z >> 1;
    const int coBase = (blockIdx.z & 1) * 64;
    const int r  = ty >> 1;
    const int c0 = (ty & 1) * 4;

    const float* inN = in + (size_t)n * CHW;
    unsigned long long acc2[2][4] = {};   // [co-pair][px], zero bits = (+0,+0)

    for (int ci0 = 0; ci0 < CCH; ci0 += 8) {
        for (int i = t; i < 800; i += 256) {
            int ci = i / 100, rem = i - ci * 100;
            int rr = rem / 10, cc = rem - rr * 10;
            int h = h0 + rr - 1, w = w0 + cc - 1;
            float v = 0.0f;
            if ((unsigned)h < 56u && (unsigned)w < 56u)
                v = inN[(ci0 + ci) * HWSZ + h * WWW + w];
            sIn[ci][rr][cc] = make_float2(v, v);
        }
        for (int i = t; i < 72 * 64; i += 256) {
            int row = i >> 6, col = i & 63;
            int ci = row / 9, kk = row - ci * 9;
            sW[row][col] = g_wq1[((ci0 + ci) * 9 + kk) * CCH + coBase + col];
        }
        __syncthreads();

        #pragma unroll 1
        for (int ci = 0; ci < 8; ci++) {
            #pragma unroll
            for (int ky = 0; ky < 3; ky++) {
                unsigned long long a[6];
                #pragma unroll
                for (int q = 0; q < 6; q++)
                    a[q] = *(const unsigned long long*)&sIn[ci][r + ky][c0 + q];
                #pragma unroll
                for (int kx = 0; kx < 3; kx++) {
                    const float* wrow = &sW[ci * 9 + ky * 3 + kx][tx * 4];
                    unsigned long long w01 = *(const unsigned long long*)(wrow);
                    unsigned long long w23 = *(const unsigned long long*)(wrow + 2);
                    #pragma unroll
                    for (int j = 0; j < 4; j++) {
                        fma_f32x2(acc2[0][j], w01, a[kx + j]);
                        fma_f32x2(acc2[1][j], w23, a[kx + j]);
                    }
                }
            }
        }
        __syncthreads();
    }

    // epilogue: unpack co-pairs, store coalesced float4 per output channel
    #pragma unroll
    for (int cp = 0; cp < 2; cp++) {
        float2 p0 = *(float2*)&acc2[cp][0];
        float2 p1 = *(float2*)&acc2[cp][1];
        float2 p2 = *(float2*)&acc2[cp][2];
        float2 p3 = *(float2*)&acc2[cp][3];
        int coL = coBase + tx * 4 + 2 * cp;
        float4 vlo = make_float4(p0.x, p1.x, p2.x, p3.x);
        float4 vhi = make_float4(p0.y, p1.y, p2.y, p3.y);
        *(float4*)&g_buf1[((size_t)n * CCH + coL) * HWSZ + (h0 + r) * WWW + w0 + c0] = vlo;
        *(float4*)&g_buf1[((size_t)n * CCH + coL + 1) * HWSZ + (h0 + r) * WWW + w0 + c0] = vhi;
    }
}

// ---------------------------------------------------------------------------
// conv2: exact int8 3x3 conv via dp4a on packed 4-bit acts.
// ---------------------------------------------------------------------------
__global__ void __launch_bounds__(256) k_conv2i()
{
    __shared__ int sIn[8][10][10];     // 8 ci4 slots = 32 real channels
    __shared__ int sW[72][64];

    const int* act = (const int*)g_buf2;

    const int t  = threadIdx.x;
    const int tx = t & 15;
    const int ty = t >> 4;
    const int w0 = blockIdx.x * 8;
    const int h0 = blockIdx.y * 8;
    const int n      = blockIdx.z >> 1;
    const int coBase = (blockIdx.z & 1) * 64;
    const int r  = ty >> 1;
    const int c0 = (ty & 1) * 4;

    const int* inN = act + (size_t)n * (NCI4 * HWSZ);
    int acc[4][4] = {};

    for (int s0 = 0; s0 < NCI4; s0 += 8) {
        for (int i = t; i < 800; i += 256) {
            int ci = i / 100, rem = i - ci * 100;
            int rr = rem / 10, cc = rem - rr * 10;
            int h = h0 + rr - 1, w = w0 + cc - 1;
            int v = 0;
            if ((unsigned)h < 56u && (unsigned)w < 56u)
                v = inN[(s0 + ci) * HWSZ + h * WWW + w];
            sIn[ci][rr][cc] = v;
        }
        for (int i = t; i < 72 * 64; i += 256) {
            int row = i >> 6, col = i & 63;
            int ci = row / 9, kk = row - ci * 9;
            sW[row][col] = g_w2p[((s0 + ci) * 9 + kk) * CCH + coBase + col];
        }
        __syncthreads();

        #pragma unroll 1
        for (int ci = 0; ci < 8; ci++) {
            #pragma unroll
            for (int ky = 0; ky < 3; ky++) {
                int a[6];
                #pragma unroll
                for (int q = 0; q < 6; q++) a[q] = sIn[ci][r + ky][c0 + q];
                #pragma unroll
                for (int kx = 0; kx < 3; kx++) {
                    const int4 wv = *(const int4*)&sW[ci * 9 + ky * 3 + kx][tx * 4];
                    #pragma unroll
                    for (int j = 0; j < 4; j++) {
                        acc[0][j] = __dp4a(wv.x, a[kx + j], acc[0][j]);
                        acc[1][j] = __dp4a(wv.y, a[kx + j], acc[1][j]);
                        acc[2][j] = __dp4a(wv.z, a[kx + j], acc[2][j]);
                        acc[3][j] = __dp4a(wv.w, a[kx + j], acc[3][j]);
                    }
                }
            }
        }
        __syncthreads();
    }

    const float sc = 1.0f / 225.0f;
    #pragma unroll
    for (int a = 0; a < 4; a++) {
        int co = coBase + tx * 4 + a;
        float4 v = make_float4((float)acc[a][0] * sc, (float)acc[a][1] * sc,
                               (float)acc[a][2] * sc, (float)acc[a][3] * sc);
        *(float4*)&g_buf1[((size_t)n * CCH + co) * HWSZ + (h0 + r) * WWW + w0 + c0] = v;
    }
}

// ---------------------------------------------------------------------------
// BN stats, stage A: per (channel, 4-image chunk) Kahan-float partials
// ---------------------------------------------------------------------------
__global__ void k_statsA() {
    const int c = blockIdx.x, j = blockIdx.y, t = threadIdx.x;
    const float* base = g_buf1 + (size_t)(4 * j) * CHW + (size_t)c * HWSZ;
    float s = 0.f, cs = 0.f, q = 0.f, cq = 0.f;
    for (int idx = t; idx < 4 * HWSZ; idx += 256) {
        int n = idx / HWSZ, p = idx - n * HWSZ;
        float v = base[(size_t)n * CHW + p];
        float y1 = v - cs, t1 = s + y1; cs = (t1 - s) - y1; s = t1;
        float v2 = v * v;
        float y2 = v2 - cq, t2 = q + y2; cq = (t2 - q) - y2; q = t2;
    }
    __shared__ double ss[256], sq[256];
    ss[t] = (double)s;
    sq[t] = (double)q;
    __syncthreads();
    for (int o = 128; o > 0; o >>= 1) {
        if (t < o) { ss[t] += ss[t + o]; sq[t] += sq[t + o]; }
        __syncthreads();
    }
    if (t == 0) { g_ps[c * 16 + j] = ss[0]; g_pq[c * 16 + j] = sq[0]; }
}

// stage B: 1 block, 128 threads; thread c reduces 16 partials in fixed order.
__global__ void k_statsB(int pass) {
    int c = threadIdx.x;
    double s = 0.0, q = 0.0;
    for (int j = 0; j < 16; j++) { s += g_ps[c * 16 + j]; q += g_pq[c * 16 + j]; }
    double m   = s / (double)NHW;
    double var = q / (double)NHW - m * m;
    g_mean[pass * CCH + c] = (float)m;
    g_istd[pass * CCH + c] = (float)(1.0 / sqrt(var + 1e-5));
}

// ---------------------------------------------------------------------------
// BN1 + 4-bit activation, output packed codes (4 channels per int32)
// ---------------------------------------------------------------------------
__global__ void k_bnpack(const float* __restrict__ gamma, const float* __restrict__ beta) {
    int i = blockIdx.x * 256 + threadIdx.x;        // packed index
    int p   = i % HWSZ;
    int ci4 = (i / HWSZ) & (NCI4 - 1);
    int n   = i / (HWSZ * NCI4);
    int pack = 0;
    #pragma unroll
    for (int b = 0; b < 4; b++) {
        int c = ci4 * 4 + b;
        float v  = (g_buf1[(size_t)n * CHW + (size_t)c * HWSZ + p] - g_mean[c]) * g_istd[c];
        v = v * gamma[c] + beta[c];
        float xc = fminf(fmaxf(v, 0.0f), 1.0f);
        int code = (int)rintf(xc * 15.0f);         // 0..15
        pack |= code << (8 * b);
    }
    ((int*)g_buf2)[i] = pack;
}

// ---------------------------------------------------------------------------
// BN2 + residual + 4-bit activation -> final output
// ---------------------------------------------------------------------------
__global__ void k_final(const float* __restrict__ x,
                        const float* __restrict__ gamma, const float* __restrict__ beta,
                        float* __restrict__ out) {
    int i = blockIdx.x * 256 + threadIdx.x;
    int c = (i / HWSZ) & (CCH - 1);
    float xn = (g_buf1[i] - g_mean[CCH + c]) * g_istd[CCH + c];
    float v  = xn * gamma[c] + beta[c] + x[i];
    float xc = fminf(fmaxf(v, 0.0f), 1.0f);
    float qq = rintf(xc * 15.0f) / 15.0f;
    out[i] = xc + (qq - xc);
}

// ---------------------------------------------------------------------------
extern "C" void kernel_launch(void* const* d_in, const int* in_sizes, int n_in,
                              void* d_out, int out_size)
{
    const float* x  = (const float*)d_in[0];
    const float* w1 = (const float*)d_in[1];
    const float* w2 = (const float*)d_in[2];
    const float* g1 = (const float*)d_in[3];
    const float* b1 = (const float*)d_in[4];
    const float* g2 = (const float*)d_in[5];
    const float* b2 = (const float*)d_in[6];
    float* out = (float*)d_out;

    k_wmax<<<2, 1024>>>(w1, w2);
    k_wquant<<<dim3(576, 2), 256>>>(w1, w2);

    dim3 cgrid(7, 7, NB * 2);
    k_conv1<<<cgrid, 256>>>(x);                       // conv1 (FFMA2) -> g_buf1
    k_statsA<<<dim3(CCH, 16), 256>>>();               // BN1 stats partials
    k_statsB<<<1, CCH>>>(0);
    k_bnpack<<<(TOTAL / 4) / 256, 256>>>(g1, b1);     // BN1 + act1 -> packed int8
    k_conv2i<<<cgrid, 256>>>();                       // conv2 (dp4a) -> g_buf1
    k_statsA<<<dim3(CCH, 16), 256>>>();               // BN2 stats partials
    k_statsB<<<1, CCH>>>(1);
    k_final<<<TOTAL / 256, 256>>>(x, g2, b2, out);    // BN2 + residual + act2
}